// round 1
// baseline (speedup 1.0000x reference)
#include <cuda_runtime.h>
#include <cstdint>

#define D 64
#define MAX_NODES 50000

// Scratch (no allocations allowed): node feature buffers + column-sum accumulator.
__device__ __align__(256) float g_h[MAX_NODES * D];
__device__ __align__(256) float g_agg[MAX_NODES * D];
__device__ __align__(256) float g_colsum[D];

// ---------------------------------------------------------------------------
// agg = h  (float4 copy; also serves as the "+h" term of GIN: agg starts at h)
// ---------------------------------------------------------------------------
__global__ void copy_f4_kernel(const float4* __restrict__ src,
                               float4* __restrict__ dst, int n4) {
    int i = blockIdx.x * blockDim.x + threadIdx.x;
    if (i < n4) dst[i] = src[i];
}

// ---------------------------------------------------------------------------
// Edge scatter: for each edge e, agg[dst[e]] += h[src[e]]  (vector f32 RED)
// One thread per (edge, 16B chunk): 16 threads cover one 256B row, coalesced.
// ---------------------------------------------------------------------------
__global__ void edge_scatter_kernel(const float* __restrict__ h,
                                    const int* __restrict__ src,
                                    const int* __restrict__ dst,
                                    float* __restrict__ agg, int n_edges) {
    int tid = blockIdx.x * blockDim.x + threadIdx.x;
    int e = tid >> 4;
    int c = tid & 15;
    if (e >= n_edges) return;
    int s = __ldg(src + e);
    int d = __ldg(dst + e);
    float4 v = *reinterpret_cast<const float4*>(h + (size_t)s * D + c * 4);
    float* p = agg + (size_t)d * D + c * 4;
    asm volatile("red.global.add.v4.f32 [%0], {%1,%2,%3,%4};"
                 :: "l"(p), "f"(v.x), "f"(v.y), "f"(v.z), "f"(v.w)
                 : "memory");
}

// ---------------------------------------------------------------------------
// Fused MLP: out = relu(r @ Wa + ba) @ Wb + bb    (all dims 64)
// Block = 256 threads = 8 warps. Each warp owns 4 rows; each lane owns 2
// adjacent output columns (c = 2*lane, 2*lane+1). Weights staged in smem and
// amortized over 4 rows per warp.
// ---------------------------------------------------------------------------
__global__ __launch_bounds__(256)
void mlp_kernel(const float* __restrict__ r, float* __restrict__ out,
                const float* __restrict__ Wa, const float* __restrict__ ba,
                const float* __restrict__ Wb, const float* __restrict__ bb,
                int n_rows) {
    __shared__ float sWa[D * D];
    __shared__ float sWb[D * D];
    __shared__ float sba[D];
    __shared__ float sbb[D];
    __shared__ float sbuf[8][4][D];  // per-warp row staging (r, then t)

    int tid = threadIdx.x;
    for (int i = tid; i < D * D; i += 256) { sWa[i] = Wa[i]; sWb[i] = Wb[i]; }
    if (tid < D) { sba[tid] = ba[tid]; sbb[tid] = bb[tid]; }
    __syncthreads();

    int warp = tid >> 5;
    int lane = tid & 31;
    int rowbase = (blockIdx.x * 8 + warp) * 4;
    if (rowbase >= n_rows) return;
    int nr = min(4, n_rows - rowbase);
    int c = lane * 2;

    // Stage rows of r into smem (each lane: 2 floats per row)
    for (int j = 0; j < nr; j++) {
        float2 v = *reinterpret_cast<const float2*>(
            r + (size_t)(rowbase + j) * D + c);
        *reinterpret_cast<float2*>(&sbuf[warp][j][c]) = v;
    }
    // Fill tail rows with zeros so uninitialized smem can't make NaNs
    for (int j = nr; j < 4; j++)
        *reinterpret_cast<float2*>(&sbuf[warp][j][c]) = make_float2(0.f, 0.f);
    __syncwarp();

    // Stage 1: t = relu(r @ Wa + ba)
    float2 acc[4];
    {
        float2 bia = *reinterpret_cast<const float2*>(&sba[c]);
        #pragma unroll
        for (int j = 0; j < 4; j++) acc[j] = bia;
        #pragma unroll 8
        for (int k = 0; k < D; k++) {
            float2 w = *reinterpret_cast<const float2*>(&sWa[k * D + c]);
            #pragma unroll
            for (int j = 0; j < 4; j++) {
                float rv = sbuf[warp][j][k];
                acc[j].x = fmaf(rv, w.x, acc[j].x);
                acc[j].y = fmaf(rv, w.y, acc[j].y);
            }
        }
    }
    __syncwarp();
    #pragma unroll
    for (int j = 0; j < 4; j++) {
        sbuf[warp][j][c]     = fmaxf(acc[j].x, 0.f);
        sbuf[warp][j][c + 1] = fmaxf(acc[j].y, 0.f);
    }
    __syncwarp();

    // Stage 2: out = t @ Wb + bb
    {
        float2 bib = *reinterpret_cast<const float2*>(&sbb[c]);
        #pragma unroll
        for (int j = 0; j < 4; j++) acc[j] = bib;
        #pragma unroll 8
        for (int k = 0; k < D; k++) {
            float2 w = *reinterpret_cast<const float2*>(&sWb[k * D + c]);
            #pragma unroll
            for (int j = 0; j < 4; j++) {
                float rv = sbuf[warp][j][k];
                acc[j].x = fmaf(rv, w.x, acc[j].x);
                acc[j].y = fmaf(rv, w.y, acc[j].y);
            }
        }
    }
    for (int j = 0; j < nr; j++) {
        *reinterpret_cast<float2*>(out + (size_t)(rowbase + j) * D + c) = acc[j];
    }
}

// ---------------------------------------------------------------------------
// Mean pooling pieces
// ---------------------------------------------------------------------------
__global__ void zero_colsum_kernel(float* p) {
    if (threadIdx.x < D) p[threadIdx.x] = 0.f;
}

__global__ void reduce_cols_kernel(const float* __restrict__ h,
                                   float* __restrict__ colsum, int n_rows) {
    __shared__ float s[256];
    int col = threadIdx.x & 63;
    int rsub = threadIdx.x >> 6;
    float acc = 0.f;
    for (int row = blockIdx.x * 4 + rsub; row < n_rows; row += gridDim.x * 4)
        acc += h[(size_t)row * D + col];
    s[threadIdx.x] = acc;
    __syncthreads();
    if (threadIdx.x < 64) {
        float v = s[threadIdx.x] + s[threadIdx.x + 64] +
                  s[threadIdx.x + 128] + s[threadIdx.x + 192];
        atomicAdd(&colsum[threadIdx.x], v);
    }
}

__global__ void final_out_kernel(const float* __restrict__ colsum,
                                 const float* __restrict__ Wout,
                                 const float* __restrict__ bout,
                                 float* __restrict__ out, int n_rows) {
    int j = threadIdx.x;
    if (j >= 16) return;
    float inv = 1.0f / (float)n_rows;
    float acc = bout[j];
    #pragma unroll
    for (int k = 0; k < D; k++)
        acc = fmaf(colsum[k] * inv, Wout[k * 16 + j], acc);
    out[j] = acc;
}

// ---------------------------------------------------------------------------
// Launch
// ---------------------------------------------------------------------------
extern "C" void kernel_launch(void* const* d_in, const int* in_sizes, int n_in,
                              void* d_out, int out_size) {
    const float* features = (const float*)d_in[0];
    const int*   src      = (const int*)d_in[1];
    const int*   dst      = (const int*)d_in[2];
    const float* Wa[3] = {(const float*)d_in[3], (const float*)d_in[7],  (const float*)d_in[11]};
    const float* ba[3] = {(const float*)d_in[4], (const float*)d_in[8],  (const float*)d_in[12]};
    const float* Wb[3] = {(const float*)d_in[5], (const float*)d_in[9],  (const float*)d_in[13]};
    const float* bb[3] = {(const float*)d_in[6], (const float*)d_in[10], (const float*)d_in[14]};
    const float* Wout = (const float*)d_in[15];
    const float* bout = (const float*)d_in[16];
    float* out = (float*)d_out;

    int n_nodes = in_sizes[0] / D;
    int n_edges = in_sizes[1];

    float *hbuf, *aggbuf, *colsum;
    cudaGetSymbolAddress((void**)&hbuf, g_h);
    cudaGetSymbolAddress((void**)&aggbuf, g_agg);
    cudaGetSymbolAddress((void**)&colsum, g_colsum);

    int n4 = n_nodes * (D / 4);
    int copy_blocks = (n4 + 255) / 256;
    int edge_threads = n_edges * 16;
    int edge_blocks = (edge_threads + 255) / 256;
    int mlp_blocks = (n_nodes + 31) / 32;

    const float* hin = features;
    for (int L = 0; L < 3; L++) {
        copy_f4_kernel<<<copy_blocks, 256>>>(
            (const float4*)hin, (float4*)aggbuf, n4);
        edge_scatter_kernel<<<edge_blocks, 256>>>(hin, src, dst, aggbuf, n_edges);
        mlp_kernel<<<mlp_blocks, 256>>>(aggbuf, hbuf, Wa[L], ba[L], Wb[L], bb[L],
                                        n_nodes);
        hin = hbuf;
    }

    zero_colsum_kernel<<<1, 64>>>(colsum);
    reduce_cols_kernel<<<256, 256>>>(hbuf, colsum, n_nodes);
    final_out_kernel<<<1, 32>>>(colsum, Wout, bout, out, n_nodes);
}